// round 1
// baseline (speedup 1.0000x reference)
#include <cuda_runtime.h>
#include <cuda_bf16.h>
#include <math.h>

// Problem constants
#define BATCH   8
#define SEQ     1024
#define DIM     768
#define HEADS   12
#define DHEAD   64
#define INNER   768
#define NQKV    2304          // 3 * INNER
#define MROWS   (BATCH*SEQ)   // 8192
#define SCALE   0.125f        // DHEAD^-0.5

// ---------------------------------------------------------------------------
// Scratch (static device globals; no runtime allocation)
// ---------------------------------------------------------------------------
__device__ float g_Q[BATCH*HEADS*SEQ*DHEAD];   // [b,h,n,d]
__device__ float g_K[BATCH*HEADS*SEQ*DHEAD];
__device__ float g_V[BATCH*HEADS*SEQ*DHEAD];
__device__ float g_AO[MROWS*INNER];            // attention out, [b*n, h*d]

// ---------------------------------------------------------------------------
// GEMM 1: C[8192,2304] = X[8192,768] @ Wqkv[768,2304], scatter into Q/K/V
// 128x128 block tile, BK=8, 256 threads, 8x8 micro-tile per thread.
// ---------------------------------------------------------------------------
__global__ __launch_bounds__(256)
void gemm_qkv_kernel(const float* __restrict__ X, const float* __restrict__ W)
{
    __shared__ float As[8][132];   // [k][m], padded
    __shared__ float Bs[8][128];   // [k][n]

    const int tid = threadIdx.x;
    const int bx = blockIdx.x;     // col tile (0..17)
    const int by = blockIdx.y;     // row tile (0..63)
    const int tx = tid & 15;
    const int ty = tid >> 4;

    const int arow = tid >> 1;          // 0..127
    const int acol = (tid & 1) * 4;     // 0 or 4
    const int brow = tid >> 5;          // 0..7
    const int bcol = (tid & 31) * 4;    // 0..124

    const float* Aptr = X + (by*128 + arow)*DIM + acol;
    const float* Bptr = W + brow*NQKV + bx*128 + bcol;

    float acc[8][8];
    #pragma unroll
    for (int i = 0; i < 8; i++)
        #pragma unroll
        for (int j = 0; j < 8; j++) acc[i][j] = 0.f;

    for (int k0 = 0; k0 < DIM; k0 += 8) {
        float4 a = *(const float4*)(Aptr + k0);
        float4 b = *(const float4*)(Bptr + (size_t)k0 * NQKV);
        As[acol+0][arow] = a.x;
        As[acol+1][arow] = a.y;
        As[acol+2][arow] = a.z;
        As[acol+3][arow] = a.w;
        *(float4*)&Bs[brow][bcol] = b;
        __syncthreads();

        #pragma unroll
        for (int kk = 0; kk < 8; kk++) {
            float4 a0 = *(const float4*)&As[kk][ty*4];
            float4 a1 = *(const float4*)&As[kk][64 + ty*4];
            float4 b0 = *(const float4*)&Bs[kk][tx*4];
            float4 b1 = *(const float4*)&Bs[kk][64 + tx*4];
            float ar[8] = {a0.x,a0.y,a0.z,a0.w, a1.x,a1.y,a1.z,a1.w};
            float br[8] = {b0.x,b0.y,b0.z,b0.w, b1.x,b1.y,b1.z,b1.w};
            #pragma unroll
            for (int i = 0; i < 8; i++)
                #pragma unroll
                for (int j = 0; j < 8; j++)
                    acc[i][j] = fmaf(ar[i], br[j], acc[i][j]);
        }
        __syncthreads();
    }

    // Scatter epilogue into Q/K/V [b,h,n,d]
    #pragma unroll
    for (int i = 0; i < 8; i++) {
        const int row = by*128 + ((i < 4) ? (ty*4 + i) : (64 + ty*4 + i - 4));
        const int b   = row >> 10;
        const int nn  = row & 1023;
        #pragma unroll
        for (int j = 0; j < 8; j++) {
            const int col = bx*128 + ((j < 4) ? (tx*4 + j) : (64 + tx*4 + j - 4));
            const int sel = col / INNER;          // 0=Q,1=K,2=V (constant per block)
            const int r   = col - sel*INNER;
            const int h   = r >> 6;
            const int d   = r & 63;
            float* dst = (sel == 0) ? g_Q : ((sel == 1) ? g_K : g_V);
            dst[(size_t)(((b*HEADS + h) << 10) + nn)*DHEAD + d] = acc[i][j];
        }
    }
}

// ---------------------------------------------------------------------------
// Flash attention: one CTA handles 64 query rows of one (b,h).
// 128 threads: tx = tid%8 (key/dhead group), ty = tid/8 (query group).
// Online softmax with 4x8 micro-tiles.
// ---------------------------------------------------------------------------
#define PADW 68
#define ATTN_SMEM (4*64*PADW*4)    // Qt + Kt + Vs + Pt = 69632 bytes

__global__ __launch_bounds__(128)
void attn_kernel()
{
    extern __shared__ float sm[];
    float* Qt = sm;                 // [d][q]  (Q^T, pre-scaled)
    float* Kt = Qt + 64*PADW;       // [d][k]  (K^T)
    float* Vs = Kt + 64*PADW;       // [k][d]
    float* Pt = Vs + 64*PADW;       // [k][q]  (P^T)

    const int bh = blockIdx.y;          // 0..95
    const int n0 = blockIdx.x * 64;
    const int tid = threadIdx.x;
    const int tx = tid & 7;             // 0..7
    const int ty = tid >> 3;            // 0..15

    const float* Qg = g_Q + (size_t)bh * SEQ * DHEAD;
    const float* Kg = g_K + (size_t)bh * SEQ * DHEAD;
    const float* Vg = g_V + (size_t)bh * SEQ * DHEAD;

    // Load Q tile transposed + scaled: Qt[d][q]
    for (int idx = tid; idx < 1024; idx += 128) {
        const int r  = idx >> 4;
        const int c4 = (idx & 15) * 4;
        float4 v = *(const float4*)(Qg + (size_t)(n0 + r)*DHEAD + c4);
        Qt[(c4+0)*PADW + r] = v.x * SCALE;
        Qt[(c4+1)*PADW + r] = v.y * SCALE;
        Qt[(c4+2)*PADW + r] = v.z * SCALE;
        Qt[(c4+3)*PADW + r] = v.w * SCALE;
    }

    float m[4], l[4], o[4][8];
    #pragma unroll
    for (int i = 0; i < 4; i++) {
        m[i] = -INFINITY; l[i] = 0.f;
        #pragma unroll
        for (int j = 0; j < 8; j++) o[i][j] = 0.f;
    }

    for (int c0 = 0; c0 < SEQ; c0 += 64) {
        __syncthreads();   // prior-iteration readers of Kt/Vs/Pt are done

        // Load K tile transposed, V tile direct
        for (int idx = tid; idx < 1024; idx += 128) {
            const int r  = idx >> 4;
            const int c4 = (idx & 15) * 4;
            float4 kv = *(const float4*)(Kg + (size_t)(c0 + r)*DHEAD + c4);
            Kt[(c4+0)*PADW + r] = kv.x;
            Kt[(c4+1)*PADW + r] = kv.y;
            Kt[(c4+2)*PADW + r] = kv.z;
            Kt[(c4+3)*PADW + r] = kv.w;
            float4 vv = *(const float4*)(Vg + (size_t)(c0 + r)*DHEAD + c4);
            *(float4*)&Vs[r*PADW + c4] = vv;
        }
        __syncthreads();

        // S = Q @ K^T  (already scaled via Q)
        float s[4][8];
        #pragma unroll
        for (int i = 0; i < 4; i++)
            #pragma unroll
            for (int j = 0; j < 8; j++) s[i][j] = 0.f;

        #pragma unroll 16
        for (int dd = 0; dd < 64; dd++) {
            float4 q  = *(const float4*)&Qt[dd*PADW + ty*4];
            float4 k0 = *(const float4*)&Kt[dd*PADW + tx*8];
            float4 k1 = *(const float4*)&Kt[dd*PADW + tx*8 + 4];
            float qa[4] = {q.x, q.y, q.z, q.w};
            float kb[8] = {k0.x,k0.y,k0.z,k0.w, k1.x,k1.y,k1.z,k1.w};
            #pragma unroll
            for (int i = 0; i < 4; i++)
                #pragma unroll
                for (int j = 0; j < 8; j++)
                    s[i][j] = fmaf(qa[i], kb[j], s[i][j]);
        }

        // Online softmax; write P^T to smem
        #pragma unroll
        for (int i = 0; i < 4; i++) {
            float mx = s[i][0];
            #pragma unroll
            for (int j = 1; j < 8; j++) mx = fmaxf(mx, s[i][j]);
            #pragma unroll
            for (int off = 4; off >= 1; off >>= 1)
                mx = fmaxf(mx, __shfl_xor_sync(0xffffffffu, mx, off, 8));
            const float mn = fmaxf(m[i], mx);
            const float alpha = __expf(m[i] - mn);
            float sum = 0.f;
            #pragma unroll
            for (int j = 0; j < 8; j++) {
                s[i][j] = __expf(s[i][j] - mn);
                sum += s[i][j];
            }
            #pragma unroll
            for (int off = 4; off >= 1; off >>= 1)
                sum += __shfl_xor_sync(0xffffffffu, sum, off, 8);
            l[i] = l[i]*alpha + sum;
            m[i] = mn;
            #pragma unroll
            for (int j = 0; j < 8; j++) o[i][j] *= alpha;
            #pragma unroll
            for (int j = 0; j < 8; j++)
                Pt[(tx*8 + j)*PADW + ty*4 + i] = s[i][j];
        }
        __syncthreads();

        // O += P @ V
        #pragma unroll 16
        for (int kk = 0; kk < 64; kk++) {
            float4 p  = *(const float4*)&Pt[kk*PADW + ty*4];
            float4 v0 = *(const float4*)&Vs[kk*PADW + tx*8];
            float4 v1 = *(const float4*)&Vs[kk*PADW + tx*8 + 4];
            float pa[4] = {p.x, p.y, p.z, p.w};
            float vb[8] = {v0.x,v0.y,v0.z,v0.w, v1.x,v1.y,v1.z,v1.w};
            #pragma unroll
            for (int i = 0; i < 4; i++)
                #pragma unroll
                for (int j = 0; j < 8; j++)
                    o[i][j] = fmaf(pa[i], vb[j], o[i][j]);
        }
    }

    // Normalize + store to g_AO [b*n, h*64 + d]
    const int b = bh / HEADS;
    const int h = bh - b*HEADS;
    #pragma unroll
    for (int i = 0; i < 4; i++) {
        const float inv = 1.f / l[i];
        const int row = b*SEQ + n0 + ty*4 + i;
        float* dst = g_AO + (size_t)row*INNER + h*DHEAD + tx*8;
        float4 o0 = make_float4(o[i][0]*inv, o[i][1]*inv, o[i][2]*inv, o[i][3]*inv);
        float4 o1 = make_float4(o[i][4]*inv, o[i][5]*inv, o[i][6]*inv, o[i][7]*inv);
        *(float4*)(dst)     = o0;
        *(float4*)(dst + 4) = o1;
    }
}

// ---------------------------------------------------------------------------
// GEMM 2: out[8192,768] = g_AO[8192,768] @ Wout[768,768] + bias
// ---------------------------------------------------------------------------
__global__ __launch_bounds__(256)
void gemm_out_kernel(const float* __restrict__ W, const float* __restrict__ bias,
                     float* __restrict__ out)
{
    __shared__ float As[8][132];
    __shared__ float Bs[8][128];

    const int tid = threadIdx.x;
    const int bx = blockIdx.x;     // 0..5
    const int by = blockIdx.y;     // 0..63
    const int tx = tid & 15;
    const int ty = tid >> 4;

    const int arow = tid >> 1;
    const int acol = (tid & 1) * 4;
    const int brow = tid >> 5;
    const int bcol = (tid & 31) * 4;

    const float* Aptr = g_AO + (size_t)(by*128 + arow)*INNER + acol;
    const float* Bptr = W + brow*DIM + bx*128 + bcol;

    float acc[8][8];
    #pragma unroll
    for (int i = 0; i < 8; i++)
        #pragma unroll
        for (int j = 0; j < 8; j++) acc[i][j] = 0.f;

    for (int k0 = 0; k0 < INNER; k0 += 8) {
        float4 a = *(const float4*)(Aptr + k0);
        float4 b = *(const float4*)(Bptr + (size_t)k0 * DIM);
        As[acol+0][arow] = a.x;
        As[acol+1][arow] = a.y;
        As[acol+2][arow] = a.z;
        As[acol+3][arow] = a.w;
        *(float4*)&Bs[brow][bcol] = b;
        __syncthreads();

        #pragma unroll
        for (int kk = 0; kk < 8; kk++) {
            float4 a0 = *(const float4*)&As[kk][ty*4];
            float4 a1 = *(const float4*)&As[kk][64 + ty*4];
            float4 b0 = *(const float4*)&Bs[kk][tx*4];
            float4 b1 = *(const float4*)&Bs[kk][64 + tx*4];
            float ar[8] = {a0.x,a0.y,a0.z,a0.w, a1.x,a1.y,a1.z,a1.w};
            float br[8] = {b0.x,b0.y,b0.z,b0.w, b1.x,b1.y,b1.z,b1.w};
            #pragma unroll
            for (int i = 0; i < 8; i++)
                #pragma unroll
                for (int j = 0; j < 8; j++)
                    acc[i][j] = fmaf(ar[i], br[j], acc[i][j]);
        }
        __syncthreads();
    }

    #pragma unroll
    for (int i = 0; i < 8; i++) {
        const int row = by*128 + ((i < 4) ? (ty*4 + i) : (64 + ty*4 + i - 4));
        #pragma unroll
        for (int j = 0; j < 8; j++) {
            const int col = bx*128 + ((j < 4) ? (tx*4 + j) : (64 + tx*4 + j - 4));
            out[(size_t)row*DIM + col] = acc[i][j] + bias[col];
        }
    }
}

// ---------------------------------------------------------------------------
// Launch
// ---------------------------------------------------------------------------
extern "C" void kernel_launch(void* const* d_in, const int* in_sizes, int n_in,
                              void* d_out, int out_size)
{
    const float* x     = (const float*)d_in[0];   // [8,1024,768]
    const float* w_qkv = (const float*)d_in[1];   // [768,2304]
    const float* w_out = (const float*)d_in[2];   // [768,768]
    const float* b_out = (const float*)d_in[3];   // [768]
    float* out = (float*)d_out;                   // [8,1024,768]

    cudaFuncSetAttribute(attn_kernel,
                         cudaFuncAttributeMaxDynamicSharedMemorySize, ATTN_SMEM);

    dim3 g1(NQKV/128, MROWS/128);     // 18 x 64
    gemm_qkv_kernel<<<g1, 256>>>(x, w_qkv);

    dim3 g2(SEQ/64, BATCH*HEADS);     // 16 x 96
    attn_kernel<<<g2, 128, ATTN_SMEM>>>();

    dim3 g3(DIM/128, MROWS/128);      // 6 x 64
    gemm_out_kernel<<<g3, 256>>>(w_out, b_out, out);
}

// round 4
// speedup vs baseline: 2.6717x; 2.6717x over previous
#include <cuda_runtime.h>
#include <cuda_bf16.h>
#include <cstdint>
#include <math.h>

#define BATCH   8
#define SEQ     1024
#define DIM     768
#define HEADS   12
#define DHEAD   64
#define INNER   768
#define NQKV    2304
#define MROWS   8192
// 0.125 * log2(e): fold softmax scale and exp->exp2 conversion into Q
#define SC_LOG2E 0.1803368801111244f

// ---------------------------------------------------------------------------
// Scratch
// ---------------------------------------------------------------------------
__device__ float g_Q[BATCH*HEADS*SEQ*DHEAD];   // [b,h,n,d]
__device__ float g_K[BATCH*HEADS*SEQ*DHEAD];
__device__ float g_V[BATCH*HEADS*SEQ*DHEAD];
__device__ float g_AO[MROWS*INNER];            // [b*n, h*d]

// ---------------------------------------------------------------------------
// Helpers
// ---------------------------------------------------------------------------
__device__ __forceinline__ uint32_t smem_u32(const void* p) {
    uint32_t a;
    asm("{ .reg .u64 t; cvta.to.shared.u64 t, %1; cvt.u32.u64 %0, t; }" : "=r"(a) : "l"(p));
    return a;
}

__device__ __forceinline__ void ldsm4(uint32_t addr, uint32_t* r) {
    asm volatile("ldmatrix.sync.aligned.m8n8.x4.shared.b16 {%0,%1,%2,%3}, [%4];"
                 : "=r"(r[0]), "=r"(r[1]), "=r"(r[2]), "=r"(r[3]) : "r"(addr));
}
__device__ __forceinline__ void ldsm4t(uint32_t addr, uint32_t* r) {
    asm volatile("ldmatrix.sync.aligned.m8n8.x4.trans.shared.b16 {%0,%1,%2,%3}, [%4];"
                 : "=r"(r[0]), "=r"(r[1]), "=r"(r[2]), "=r"(r[3]) : "r"(addr));
}
__device__ __forceinline__ void mma16816(float* c, const uint32_t* a, uint32_t b0, uint32_t b1) {
    asm volatile("mma.sync.aligned.m16n8k16.row.col.f32.bf16.bf16.f32 "
                 "{%0,%1,%2,%3}, {%4,%5,%6,%7}, {%8,%9}, {%0,%1,%2,%3};"
                 : "+f"(c[0]), "+f"(c[1]), "+f"(c[2]), "+f"(c[3])
                 : "r"(a[0]), "r"(a[1]), "r"(a[2]), "r"(a[3]), "r"(b0), "r"(b1));
}
__device__ __forceinline__ float fast_exp2(float x) {
    float y;
    asm("ex2.approx.f32 %0, %1;" : "=f"(y) : "f"(x));
    return y;
}
// split v into hi(bf16) + lo(bf16)
__device__ __forceinline__ void split2_store(char* hi_p, char* lo_p, float x, float y) {
    __nv_bfloat16 hx = __float2bfloat16(x);
    __nv_bfloat16 hy = __float2bfloat16(y);
    float lx = x - __bfloat162float(hx);
    float ly = y - __bfloat162float(hy);
    *(__nv_bfloat162*)hi_p = __nv_bfloat162(hx, hy);
    *(__nv_bfloat162*)lo_p = __nv_bfloat162(__float2bfloat16(lx), __float2bfloat16(ly));
}

// ---------------------------------------------------------------------------
// GEMM: C[8192, N] = A[8192,768] @ W[768, N]   (split-bf16, 3-pass HMMA)
// MODE 0: A = param, scatter into g_Q/g_K/g_V (N=2304).
// MODE 1: A = g_AO (device global resolved in device code!), out = C + bias.
// CTA tile 128x128, 8 warps (4m x 2n), K chunk 64.
// A smem: [128 m][72 k] bf16 (hi,lo).  B smem: [64 k][136 n] bf16 (hi,lo).
// ---------------------------------------------------------------------------
#define GA_S 72
#define GB_S 136
#define G_AHI 0
#define G_ALO 18432
#define G_BHI 36864
#define G_BLO 54272
#define G_SMEM_BYTES 71680

template<int MODE>
__global__ void __launch_bounds__(256, 2)
gemm_tc(const float* __restrict__ Ain, const float* __restrict__ W,
        int ldw, const float* __restrict__ bias, float* __restrict__ out)
{
    extern __shared__ char smem[];
    const uint32_t sb = smem_u32(smem);
    const int tid  = threadIdx.x;
    const int lane = tid & 31;
    const int wid  = tid >> 5;
    const int wm   = wid & 3;     // m warp 0..3 (32 rows each)
    const int wn   = wid >> 2;    // n warp 0..1 (64 cols each)
    const int bx = blockIdx.x, by = blockIdx.y;

    // CRITICAL: device-global scratch must be resolved in DEVICE code.
    const float* A = (MODE == 1) ? (const float*)g_AO : Ain;

    float acc[2][8][4];
    #pragma unroll
    for (int i = 0; i < 2; i++)
        #pragma unroll
        for (int j = 0; j < 8; j++)
            #pragma unroll
            for (int k = 0; k < 4; k++) acc[i][j][k] = 0.f;

    const int lrow = lane & 15;
    const int lc16 = (lane >> 4) * 16;     // byte offset for k/n +8 block

    // ldmatrix base addresses
    const uint32_t aAhi = sb + G_AHI + (uint32_t)((wm*32 + lrow)*GA_S)*2 + lc16;
    const uint32_t aAlo = aAhi + (G_ALO - G_AHI);
    const uint32_t aBhi = sb + G_BHI + (uint32_t)(lrow*GB_S)*2 + lc16 + (uint32_t)(wn*64)*2;
    const uint32_t aBlo = aBhi + (G_BLO - G_BHI);

    for (int ch = 0; ch < 12; ch++) {
        const int k0 = ch * 64;
        __syncthreads();
        // Load A tile: 128 rows x 64 k fp32 -> hi/lo bf16
        #pragma unroll
        for (int i = tid; i < 4096; i += 256) {
            const int row = i >> 5, kp = i & 31;
            float2 v = *(const float2*)(A + (size_t)(by*128 + row)*768 + k0 + kp*2);
            const uint32_t off = (uint32_t)(row*GA_S + kp*2)*2;
            split2_store(smem + G_AHI + off, smem + G_ALO + off, v.x, v.y);
        }
        // Load B tile: 64 k x 128 n fp32 -> hi/lo bf16 (natural [k][n] layout)
        #pragma unroll
        for (int i = tid; i < 4096; i += 256) {
            const int k = i >> 6, np = i & 63;
            float2 v = *(const float2*)(W + (size_t)(k0 + k)*ldw + bx*128 + np*2);
            const uint32_t off = (uint32_t)(k*GB_S + np*2)*2;
            split2_store(smem + G_BHI + off, smem + G_BLO + off, v.x, v.y);
        }
        __syncthreads();

        #pragma unroll
        for (int ks = 0; ks < 4; ks++) {
            uint32_t ah[2][4], al[2][4];
            ldsm4(aAhi + ks*32,             ah[0]);
            ldsm4(aAhi + 16*GA_S*2 + ks*32, ah[1]);
            ldsm4(aAlo + ks*32,             al[0]);
            ldsm4(aAlo + 16*GA_S*2 + ks*32, al[1]);
            #pragma unroll
            for (int np = 0; np < 4; np++) {
                uint32_t bh[4], bl[4];
                ldsm4t(aBhi + ks*16*GB_S*2 + np*32, bh);
                ldsm4t(aBlo + ks*16*GB_S*2 + np*32, bl);
                // trans pairing: n-tile0 = {r0,r1}, n-tile1 = {r2,r3}
                #pragma unroll
                for (int mt = 0; mt < 2; mt++) {
                    mma16816(acc[mt][np*2+0], ah[mt], bh[0], bh[1]);  // hh
                    mma16816(acc[mt][np*2+1], ah[mt], bh[2], bh[3]);
                    mma16816(acc[mt][np*2+0], ah[mt], bl[0], bl[1]);  // hl
                    mma16816(acc[mt][np*2+1], ah[mt], bl[2], bl[3]);
                    mma16816(acc[mt][np*2+0], al[mt], bh[0], bh[1]);  // lh
                    mma16816(acc[mt][np*2+1], al[mt], bh[2], bh[3]);
                }
            }
        }
    }

    // Epilogue
    #pragma unroll
    for (int mt = 0; mt < 2; mt++) {
        const int row0 = by*128 + wm*32 + mt*16 + (lane >> 2);
        #pragma unroll
        for (int nt = 0; nt < 8; nt++) {
            const int col = bx*128 + wn*64 + nt*8 + (lane & 3)*2;
            if (MODE == 0) {
                const int sel = col / INNER;
                float* dst = (sel == 0) ? g_Q : ((sel == 1) ? g_K : g_V);
                const int cr = col - sel*INNER;
                const int h = cr >> 6, d = cr & 63;
                {
                    const int b = row0 >> 10, nn = row0 & 1023;
                    *(float2*)&dst[(size_t)(((b*HEADS + h) << 10) + nn)*DHEAD + d] =
                        make_float2(acc[mt][nt][0], acc[mt][nt][1]);
                }
                {
                    const int r1 = row0 + 8;
                    const int b = r1 >> 10, nn = r1 & 1023;
                    *(float2*)&dst[(size_t)(((b*HEADS + h) << 10) + nn)*DHEAD + d] =
                        make_float2(acc[mt][nt][2], acc[mt][nt][3]);
                }
            } else {
                const float b0 = bias[col], b1 = bias[col+1];
                *(float2*)&out[(size_t)row0*DIM + col] =
                    make_float2(acc[mt][nt][0] + b0, acc[mt][nt][1] + b1);
                *(float2*)&out[(size_t)(row0+8)*DIM + col] =
                    make_float2(acc[mt][nt][2] + b0, acc[mt][nt][3] + b1);
            }
        }
    }
}

// ---------------------------------------------------------------------------
// Attention (HMMA, unnormalized log2-domain softmax, O in registers)
// CTA: 128 queries of one (b,h), 16 chunks of 64 keys, 256 threads (8 warps).
// Warp grid 4m x 2n. S tile 128x64, O tile 128x64.
// ---------------------------------------------------------------------------
#define AT_QHI 0
#define AT_QLO 18432
#define AT_KHI 36864
#define AT_KLO 46080
#define AT_VHI 55296
#define AT_VLO 64512
#define AT_PHI 73728
#define AT_PLO 92160
#define AT_RSP 110592   // float[2][128] row-sum partials
#define AT_RSA 111616   // float[128]   row-sum accumulator
#define A_SMEM_BYTES 112128

__global__ void __launch_bounds__(256, 1)
attn_tc()
{
    extern __shared__ char smem[];
    const uint32_t sb = smem_u32(smem);
    const int tid  = threadIdx.x;
    const int lane = tid & 31;
    const int wid  = tid >> 5;
    const int wm   = wid & 3;    // 32 q rows
    const int wn   = wid >> 2;   // 32 key cols (S) / 32 d cols (O)
    const int bh = blockIdx.y;
    const int q0 = blockIdx.x * 128;

    const float* Qg = g_Q + (size_t)bh * SEQ * DHEAD;
    const float* Kg = g_K + (size_t)bh * SEQ * DHEAD;
    const float* Vg = g_V + (size_t)bh * SEQ * DHEAD;

    float* rsp = (float*)(smem + AT_RSP);
    float* rsa = (float*)(smem + AT_RSA);
    if (tid < 128) rsa[tid] = 0.f;

    // Q tile: 128 q x 64 d, scaled by SC_LOG2E, split hi/lo
    #pragma unroll
    for (int i = tid; i < 4096; i += 256) {
        const int row = i >> 5, kp = i & 31;
        float2 v = *(const float2*)(Qg + (size_t)(q0 + row)*DHEAD + kp*2);
        const uint32_t off = (uint32_t)(row*72 + kp*2)*2;
        split2_store(smem + AT_QHI + off, smem + AT_QLO + off,
                     v.x * SC_LOG2E, v.y * SC_LOG2E);
    }

    float o[2][4][4];
    #pragma unroll
    for (int i = 0; i < 2; i++)
        #pragma unroll
        for (int j = 0; j < 4; j++)
            #pragma unroll
            for (int k = 0; k < 4; k++) o[i][j][k] = 0.f;

    const int lrow = lane & 15;
    const int lc16 = (lane >> 4) * 16;
    const uint32_t aQhi = sb + AT_QHI + (uint32_t)((wm*32 + lrow)*72)*2 + lc16;
    const uint32_t aQlo = aQhi + (AT_QLO - AT_QHI);
    const uint32_t aKhi = sb + AT_KHI + (uint32_t)((wn*32 + lrow)*72)*2 + lc16;
    const uint32_t aKlo = aKhi + (AT_KLO - AT_KHI);
    const uint32_t aVhi = sb + AT_VHI + (uint32_t)(lrow*72)*2 + lc16 + (uint32_t)(wn*32)*2;
    const uint32_t aVlo = aVhi + (AT_VLO - AT_VHI);
    const uint32_t aPhi = sb + AT_PHI + (uint32_t)((wm*32 + lrow)*72)*2 + lc16;
    const uint32_t aPlo = aPhi + (AT_PLO - AT_PHI);

    for (int c = 0; c < 16; c++) {
        const int key0 = c * 64;
        __syncthreads();
        // Load K, V chunks (natural [key][d] layout, pad 72)
        #pragma unroll
        for (int i = tid; i < 2048; i += 256) {
            const int row = i >> 5, kp = i & 31;
            const uint32_t off = (uint32_t)(row*72 + kp*2)*2;
            float2 kv = *(const float2*)(Kg + (size_t)(key0 + row)*DHEAD + kp*2);
            split2_store(smem + AT_KHI + off, smem + AT_KLO + off, kv.x, kv.y);
            float2 vv = *(const float2*)(Vg + (size_t)(key0 + row)*DHEAD + kp*2);
            split2_store(smem + AT_VHI + off, smem + AT_VLO + off, vv.x, vv.y);
        }
        __syncthreads();

        // S = Q @ K^T  (K non-trans ldmatrix: B = [n=key][k=d] natural layout)
        float s[2][4][4];
        #pragma unroll
        for (int i = 0; i < 2; i++)
            #pragma unroll
            for (int j = 0; j < 4; j++)
                #pragma unroll
                for (int k = 0; k < 4; k++) s[i][j][k] = 0.f;

        #pragma unroll
        for (int ks = 0; ks < 4; ks++) {
            uint32_t qh[2][4], ql[2][4];
            ldsm4(aQhi + ks*32,          qh[0]);
            ldsm4(aQhi + 16*144 + ks*32, qh[1]);
            ldsm4(aQlo + ks*32,          ql[0]);
            ldsm4(aQlo + 16*144 + ks*32, ql[1]);
            #pragma unroll
            for (int np = 0; np < 2; np++) {
                uint32_t kh[4], kl[4];
                ldsm4(aKhi + np*16*144 + ks*32, kh);
                ldsm4(aKlo + np*16*144 + ks*32, kl);
                // non-trans pairing: n-tile0 = {r0,r2}, n-tile1 = {r1,r3}
                #pragma unroll
                for (int mt = 0; mt < 2; mt++) {
                    mma16816(s[mt][np*2+0], qh[mt], kh[0], kh[2]);
                    mma16816(s[mt][np*2+1], qh[mt], kh[1], kh[3]);
                    mma16816(s[mt][np*2+0], qh[mt], kl[0], kl[2]);
                    mma16816(s[mt][np*2+1], qh[mt], kl[1], kl[3]);
                    mma16816(s[mt][np*2+0], ql[mt], kh[0], kh[2]);
                    mma16816(s[mt][np*2+1], ql[mt], kh[1], kh[3]);
                }
            }
        }

        // P = 2^S, row-sum partials, P -> smem (hi/lo)
        #pragma unroll
        for (int mt = 0; mt < 2; mt++) {
            float rs0 = 0.f, rs1 = 0.f;
            const int prow = wm*32 + mt*16 + (lane >> 2);
            #pragma unroll
            for (int nt = 0; nt < 4; nt++) {
                const float e0 = fast_exp2(s[mt][nt][0]);
                const float e1 = fast_exp2(s[mt][nt][1]);
                const float e2 = fast_exp2(s[mt][nt][2]);
                const float e3 = fast_exp2(s[mt][nt][3]);
                rs0 += e0 + e1;
                rs1 += e2 + e3;
                const int pcol = wn*32 + nt*8 + (lane & 3)*2;
                const uint32_t off0 = (uint32_t)(prow*72 + pcol)*2;
                split2_store(smem + AT_PHI + off0, smem + AT_PLO + off0, e0, e1);
                const uint32_t off1 = off0 + 8*144;
                split2_store(smem + AT_PHI + off1, smem + AT_PLO + off1, e2, e3);
            }
            rs0 += __shfl_xor_sync(0xffffffffu, rs0, 1);
            rs0 += __shfl_xor_sync(0xffffffffu, rs0, 2);
            rs1 += __shfl_xor_sync(0xffffffffu, rs1, 1);
            rs1 += __shfl_xor_sync(0xffffffffu, rs1, 2);
            if ((lane & 3) == 0) {
                rsp[wn*128 + prow]     = rs0;
                rsp[wn*128 + prow + 8] = rs1;
            }
        }
        __syncthreads();
        if (tid < 128) rsa[tid] += rsp[tid] + rsp[128 + tid];

        // O += P @ V  (V trans ldmatrix: B = [k=key][n=d] natural layout)
        #pragma unroll
        for (int ks = 0; ks < 4; ks++) {
            uint32_t ph[2][4], pl[2][4];
            ldsm4(aPhi + ks*32,          ph[0]);
            ldsm4(aPhi + 16*144 + ks*32, ph[1]);
            ldsm4(aPlo + ks*32,          pl[0]);
            ldsm4(aPlo + 16*144 + ks*32, pl[1]);
            #pragma unroll
            for (int np = 0; np < 2; np++) {
                uint32_t vh[4], vl[4];
                ldsm4t(aVhi + ks*16*144 + np*32, vh);
                ldsm4t(aVlo + ks*16*144 + np*32, vl);
                // trans pairing: n-tile0 = {r0,r1}, n-tile1 = {r2,r3}
                #pragma unroll
                for (int mt = 0; mt < 2; mt++) {
                    mma16816(o[mt][np*2+0], ph[mt], vh[0], vh[1]);
                    mma16816(o[mt][np*2+1], ph[mt], vh[2], vh[3]);
                    mma16816(o[mt][np*2+0], ph[mt], vl[0], vl[1]);
                    mma16816(o[mt][np*2+1], ph[mt], vl[2], vl[3]);
                    mma16816(o[mt][np*2+0], pl[mt], vh[0], vh[1]);
                    mma16816(o[mt][np*2+1], pl[mt], vh[2], vh[3]);
                }
            }
        }
    }
    __syncthreads();

    // Normalize + store to g_AO
    const int b = bh / HEADS;
    const int h = bh - b*HEADS;
    #pragma unroll
    for (int mt = 0; mt < 2; mt++) {
        const int row0 = wm*32 + mt*16 + (lane >> 2);
        const float inv0 = 1.f / rsa[row0];
        const float inv1 = 1.f / rsa[row0 + 8];
        #pragma unroll
        for (int nt = 0; nt < 4; nt++) {
            const int d = wn*32 + nt*8 + (lane & 3)*2;
            float* dst0 = g_AO + (size_t)(b*SEQ + q0 + row0)*INNER + h*DHEAD + d;
            *(float2*)dst0 = make_float2(o[mt][nt][0]*inv0, o[mt][nt][1]*inv0);
            float* dst1 = g_AO + (size_t)(b*SEQ + q0 + row0 + 8)*INNER + h*DHEAD + d;
            *(float2*)dst1 = make_float2(o[mt][nt][2]*inv1, o[mt][nt][3]*inv1);
        }
    }
}

// ---------------------------------------------------------------------------
// Launch
// ---------------------------------------------------------------------------
extern "C" void kernel_launch(void* const* d_in, const int* in_sizes, int n_in,
                              void* d_out, int out_size)
{
    const float* x     = (const float*)d_in[0];
    const float* w_qkv = (const float*)d_in[1];
    const float* w_out = (const float*)d_in[2];
    const float* b_out = (const float*)d_in[3];
    float* out = (float*)d_out;

    cudaFuncSetAttribute(gemm_tc<0>, cudaFuncAttributeMaxDynamicSharedMemorySize, G_SMEM_BYTES);
    cudaFuncSetAttribute(gemm_tc<1>, cudaFuncAttributeMaxDynamicSharedMemorySize, G_SMEM_BYTES);
    cudaFuncSetAttribute(attn_tc,    cudaFuncAttributeMaxDynamicSharedMemorySize, A_SMEM_BYTES);

    dim3 g1(NQKV/128, MROWS/128);   // 18 x 64
    gemm_tc<0><<<g1, 256, G_SMEM_BYTES>>>(x, w_qkv, NQKV, nullptr, nullptr);

    dim3 g2(SEQ/128, BATCH*HEADS);  // 8 x 96
    attn_tc<<<g2, 256, A_SMEM_BYTES>>>();

    dim3 g3(DIM/128, MROWS/128);    // 6 x 64
    gemm_tc<1><<<g3, 256, G_SMEM_BYTES>>>(nullptr, w_out, DIM, b_out, out);
}

// round 5
// speedup vs baseline: 2.8945x; 1.0834x over previous
#include <cuda_runtime.h>
#include <cuda_bf16.h>
#include <cstdint>
#include <math.h>

#define BATCH   8
#define SEQ     1024
#define DIM     768
#define HEADS   12
#define DHEAD   64
#define INNER   768
#define NQKV    2304
#define MROWS   8192
// 0.125 * log2(e): fold softmax scale and exp->exp2 conversion into Q
#define SC_LOG2E 0.1803368801111244f

// ---------------------------------------------------------------------------
// Persistent bf16 hi/lo scratch (split representation: x ~= hi + lo)
// ---------------------------------------------------------------------------
__device__ __nv_bfloat16 g_Xhi[MROWS*DIM],   g_Xlo[MROWS*DIM];
__device__ __nv_bfloat16 g_WQhi[DIM*NQKV],   g_WQlo[DIM*NQKV];
__device__ __nv_bfloat16 g_WOhi[INNER*DIM],  g_WOlo[INNER*DIM];
__device__ __nv_bfloat16 g_Qhi[BATCH*HEADS*SEQ*DHEAD], g_Qlo[BATCH*HEADS*SEQ*DHEAD];
__device__ __nv_bfloat16 g_Khi[BATCH*HEADS*SEQ*DHEAD], g_Klo[BATCH*HEADS*SEQ*DHEAD];
__device__ __nv_bfloat16 g_Vhi[BATCH*HEADS*SEQ*DHEAD], g_Vlo[BATCH*HEADS*SEQ*DHEAD];
__device__ __nv_bfloat16 g_AOhi[MROWS*INNER], g_AOlo[MROWS*INNER];

// ---------------------------------------------------------------------------
// Helpers
// ---------------------------------------------------------------------------
__device__ __forceinline__ uint32_t smem_u32(const void* p) {
    uint32_t a;
    asm("{ .reg .u64 t; cvta.to.shared.u64 t, %1; cvt.u32.u64 %0, t; }" : "=r"(a) : "l"(p));
    return a;
}
__device__ __forceinline__ void ldsm4(uint32_t addr, uint32_t* r) {
    asm volatile("ldmatrix.sync.aligned.m8n8.x4.shared.b16 {%0,%1,%2,%3}, [%4];"
                 : "=r"(r[0]), "=r"(r[1]), "=r"(r[2]), "=r"(r[3]) : "r"(addr));
}
__device__ __forceinline__ void ldsm4t(uint32_t addr, uint32_t* r) {
    asm volatile("ldmatrix.sync.aligned.m8n8.x4.trans.shared.b16 {%0,%1,%2,%3}, [%4];"
                 : "=r"(r[0]), "=r"(r[1]), "=r"(r[2]), "=r"(r[3]) : "r"(addr));
}
__device__ __forceinline__ void mma16816(float* c, const uint32_t* a, uint32_t b0, uint32_t b1) {
    asm volatile("mma.sync.aligned.m16n8k16.row.col.f32.bf16.bf16.f32 "
                 "{%0,%1,%2,%3}, {%4,%5,%6,%7}, {%8,%9}, {%0,%1,%2,%3};"
                 : "+f"(c[0]), "+f"(c[1]), "+f"(c[2]), "+f"(c[3])
                 : "r"(a[0]), "r"(a[1]), "r"(a[2]), "r"(a[3]), "r"(b0), "r"(b1));
}
__device__ __forceinline__ float fast_exp2(float x) {
    float y;
    asm("ex2.approx.f32 %0, %1;" : "=f"(y) : "f"(x));
    return y;
}
__device__ __forceinline__ void cpa16(uint32_t dst, const void* src) {
    asm volatile("cp.async.cg.shared.global [%0], [%1], 16;" :: "r"(dst), "l"(src));
}
#define CP_COMMIT() asm volatile("cp.async.commit_group;" ::: "memory")

// split (x,y) -> packed bf16x2 hi / lo
__device__ __forceinline__ void split_pack(float x, float y,
                                           __nv_bfloat162& h2, __nv_bfloat162& l2) {
    __nv_bfloat16 hx = __float2bfloat16(x);
    __nv_bfloat16 hy = __float2bfloat16(y);
    h2 = __nv_bfloat162(hx, hy);
    l2 = __nv_bfloat162(__float2bfloat16(x - __bfloat162float(hx)),
                        __float2bfloat16(y - __bfloat162float(hy)));
}
// smem direct split store (for P tile)
__device__ __forceinline__ void split2_store(char* hi_p, char* lo_p, float x, float y) {
    __nv_bfloat162 h2, l2;
    split_pack(x, y, h2, l2);
    *(__nv_bfloat162*)hi_p = h2;
    *(__nv_bfloat162*)lo_p = l2;
}

// ---------------------------------------------------------------------------
// Pre-convert: fp32 -> bf16 hi/lo, once per input tensor
// SEL 0: X, SEL 1: W_qkv, SEL 2: W_out  (targets resolved in device code)
// ---------------------------------------------------------------------------
template<int SEL>
__global__ void cvt_split(const float* __restrict__ src, int n)
{
    __nv_bfloat16* hi = (SEL == 0) ? g_Xhi : (SEL == 1) ? g_WQhi : g_WOhi;
    __nv_bfloat16* lo = (SEL == 0) ? g_Xlo : (SEL == 1) ? g_WQlo : g_WOlo;
    const int i = (blockIdx.x * blockDim.x + threadIdx.x) * 4;
    if (i < n) {
        float4 v = *(const float4*)(src + i);
        __nv_bfloat162 h0, l0, h1, l1;
        split_pack(v.x, v.y, h0, l0);
        split_pack(v.z, v.w, h1, l1);
        *(__nv_bfloat162*)(hi + i)     = h0;
        *(__nv_bfloat162*)(hi + i + 2) = h1;
        *(__nv_bfloat162*)(lo + i)     = l0;
        *(__nv_bfloat162*)(lo + i + 2) = l1;
    }
}

// ---------------------------------------------------------------------------
// GEMM (split-bf16 3-pass HMMA, cp.async double-buffered)
// MODE 0: C = X @ Wqkv (N=2304), scatter Q(scaled)/K/V as bf16 hi/lo
// MODE 1: C = AO @ Wout + bias (N=768), fp32 out
// CTA tile 128x128, 8 warps (4m x 2n), K chunk 64, 2 smem stages.
// Stage: Ahi[128x72] Alo | Bhi[64x136] Blo  (bf16, padded rows)
// ---------------------------------------------------------------------------
#define G_AHI 0
#define G_ALO 18432
#define G_BHI 36864
#define G_BLO 54272
#define G_STAGE 71680
#define G_SMEM_BYTES (2*G_STAGE)

template<int MODE>
__global__ void __launch_bounds__(256, 1)
gemm_tc(const float* __restrict__ bias, float* __restrict__ out)
{
    extern __shared__ char smem[];
    const uint32_t sb = smem_u32(smem);
    const int tid  = threadIdx.x;
    const int lane = tid & 31;
    const int wid  = tid >> 5;
    const int wm   = wid & 3;
    const int wn   = wid >> 2;
    const int bx = blockIdx.x, by = blockIdx.y;

    const __nv_bfloat16* Ahi = (MODE == 0) ? g_Xhi  : g_AOhi;
    const __nv_bfloat16* Alo = (MODE == 0) ? g_Xlo  : g_AOlo;
    const __nv_bfloat16* Bhi = (MODE == 0) ? g_WQhi : g_WOhi;
    const __nv_bfloat16* Blo = (MODE == 0) ? g_WQlo : g_WOlo;
    const int ldb = (MODE == 0) ? NQKV : DIM;

    float acc[2][8][4];
    #pragma unroll
    for (int i = 0; i < 2; i++)
        #pragma unroll
        for (int j = 0; j < 8; j++)
            #pragma unroll
            for (int k = 0; k < 4; k++) acc[i][j][k] = 0.f;

    const int lrow = lane & 15;
    const int lc16 = (lane >> 4) * 16;
    const uint32_t aAhi = sb + G_AHI + (uint32_t)((wm*32 + lrow)*144) + lc16;
    const uint32_t aBhi = sb + G_BHI + (uint32_t)(lrow*272) + lc16 + (uint32_t)(wn*128);

    // prefetch chunk ch into stage st
    auto prefetch = [&](int ch, int st) {
        const int k0 = ch * 64;
        const uint32_t sa = sb + (uint32_t)st * G_STAGE;
        #pragma unroll
        for (int i = tid; i < 1024; i += 256) {
            const int row = i >> 3, seg = i & 7;
            const uint32_t d = sa + G_AHI + row*144 + seg*16;
            const size_t g = (size_t)(by*128 + row)*768 + k0 + seg*8;
            cpa16(d,                 Ahi + g);
            cpa16(d + (G_ALO-G_AHI), Alo + g);
        }
        #pragma unroll
        for (int i = tid; i < 1024; i += 256) {
            const int row = i >> 4, seg = i & 15;
            const uint32_t d = sa + G_BHI + row*272 + seg*16;
            const size_t g = (size_t)(k0 + row)*ldb + bx*128 + seg*8;
            cpa16(d,                 Bhi + g);
            cpa16(d + (G_BLO-G_BHI), Blo + g);
        }
    };

    prefetch(0, 0);
    CP_COMMIT();

    for (int ch = 0; ch < 12; ch++) {
        if (ch + 1 < 12) { prefetch(ch + 1, (ch + 1) & 1); CP_COMMIT(); }
        if (ch + 1 < 12) { asm volatile("cp.async.wait_group 1;" ::: "memory"); }
        else             { asm volatile("cp.async.wait_group 0;" ::: "memory"); }
        __syncthreads();

        const uint32_t so = (uint32_t)(ch & 1) * G_STAGE;
        #pragma unroll
        for (int ks = 0; ks < 4; ks++) {
            uint32_t ah[2][4], al[2][4];
            ldsm4(aAhi + so + ks*32,              ah[0]);
            ldsm4(aAhi + so + 16*144 + ks*32,     ah[1]);
            ldsm4(aAhi + so + (G_ALO-G_AHI) + ks*32,          al[0]);
            ldsm4(aAhi + so + (G_ALO-G_AHI) + 16*144 + ks*32, al[1]);
            #pragma unroll
            for (int np = 0; np < 4; np++) {
                uint32_t bh[4], bl[4];
                ldsm4t(aBhi + so + ks*4352 + np*32, bh);
                ldsm4t(aBhi + so + (G_BLO-G_BHI) + ks*4352 + np*32, bl);
                #pragma unroll
                for (int mt = 0; mt < 2; mt++) {
                    mma16816(acc[mt][np*2+0], ah[mt], bh[0], bh[1]);  // hh
                    mma16816(acc[mt][np*2+1], ah[mt], bh[2], bh[3]);
                    mma16816(acc[mt][np*2+0], ah[mt], bl[0], bl[1]);  // hl
                    mma16816(acc[mt][np*2+1], ah[mt], bl[2], bl[3]);
                    mma16816(acc[mt][np*2+0], al[mt], bh[0], bh[1]);  // lh
                    mma16816(acc[mt][np*2+1], al[mt], bh[2], bh[3]);
                }
            }
        }
        __syncthreads();   // all reads of this stage done before it is overwritten
    }

    // Epilogue
    #pragma unroll
    for (int mt = 0; mt < 2; mt++) {
        const int row0 = by*128 + wm*32 + mt*16 + (lane >> 2);
        #pragma unroll
        for (int nt = 0; nt < 8; nt++) {
            const int col = bx*128 + wn*64 + nt*8 + (lane & 3)*2;
            if (MODE == 0) {
                const int sel = col / INNER;
                __nv_bfloat16* dhi = (sel == 0) ? g_Qhi : (sel == 1) ? g_Khi : g_Vhi;
                __nv_bfloat16* dlo = (sel == 0) ? g_Qlo : (sel == 1) ? g_Klo : g_Vlo;
                const float sc = (sel == 0) ? SC_LOG2E : 1.f;  // fold softmax scale into Q
                const int cr = col - sel*INNER;
                const int h = cr >> 6, d = cr & 63;
                {
                    const int b = row0 >> 10, nn = row0 & 1023;
                    const size_t idx = (size_t)(((b*HEADS + h) << 10) + nn)*DHEAD + d;
                    __nv_bfloat162 h2, l2;
                    split_pack(acc[mt][nt][0]*sc, acc[mt][nt][1]*sc, h2, l2);
                    *(__nv_bfloat162*)(dhi + idx) = h2;
                    *(__nv_bfloat162*)(dlo + idx) = l2;
                }
                {
                    const int r1 = row0 + 8;
                    const int b = r1 >> 10, nn = r1 & 1023;
                    const size_t idx = (size_t)(((b*HEADS + h) << 10) + nn)*DHEAD + d;
                    __nv_bfloat162 h2, l2;
                    split_pack(acc[mt][nt][2]*sc, acc[mt][nt][3]*sc, h2, l2);
                    *(__nv_bfloat162*)(dhi + idx) = h2;
                    *(__nv_bfloat162*)(dlo + idx) = l2;
                }
            } else {
                const float b0 = bias[col], b1 = bias[col+1];
                *(float2*)&out[(size_t)row0*DIM + col] =
                    make_float2(acc[mt][nt][0] + b0, acc[mt][nt][1] + b1);
                *(float2*)&out[(size_t)(row0+8)*DIM + col] =
                    make_float2(acc[mt][nt][2] + b0, acc[mt][nt][3] + b1);
            }
        }
    }
}

// ---------------------------------------------------------------------------
// Attention (HMMA, unnormalized log2-domain softmax, cp.async double-buffered)
// CTA: 128 queries of one (b,h), 16 chunks of 64 keys, 256 threads (8 warps).
// Q pre-scaled (SC_LOG2E folded at QKV epilogue). O accumulated in registers.
// ---------------------------------------------------------------------------
#define A_QHI 0
#define A_QLO 18432
#define A_KV0 36864
#define A_KHIo 0
#define A_KLOo 9216
#define A_VHIo 18432
#define A_VLOo 27648
#define A_STAGE 36864
#define A_PHI 110592
#define A_PLO 129024
#define A_RSP 147456
#define A_RSA 148480
#define A_SMEM_BYTES 148992

__global__ void __launch_bounds__(256, 1)
attn_tc()
{
    extern __shared__ char smem[];
    const uint32_t sb = smem_u32(smem);
    const int tid  = threadIdx.x;
    const int lane = tid & 31;
    const int wid  = tid >> 5;
    const int wm   = wid & 3;
    const int wn   = wid >> 2;
    const int bh = blockIdx.y;
    const int q0 = blockIdx.x * 128;

    float* rsp = (float*)(smem + A_RSP);
    float* rsa = (float*)(smem + A_RSA);
    if (tid < 128) rsa[tid] = 0.f;

    const size_t qbase = ((size_t)bh*SEQ + q0) * DHEAD;

    // KV chunk prefetch into stage st
    auto prefetchKV = [&](int c, int st) {
        const size_t g0 = ((size_t)bh*SEQ + c*64) * DHEAD;
        const uint32_t sa = sb + A_KV0 + (uint32_t)st * A_STAGE;
        #pragma unroll
        for (int i = tid; i < 512; i += 256) {
            const int row = i >> 3, seg = i & 7;
            const uint32_t d = sa + row*144 + seg*16;
            const size_t g = g0 + row*64 + seg*8;
            cpa16(d + A_KHIo, g_Khi + g);
            cpa16(d + A_KLOo, g_Klo + g);
            cpa16(d + A_VHIo, g_Vhi + g);
            cpa16(d + A_VLOo, g_Vlo + g);
        }
    };

    // Q tile + first KV chunk in one group
    #pragma unroll
    for (int i = tid; i < 1024; i += 256) {
        const int row = i >> 3, seg = i & 7;
        const uint32_t d = sb + A_QHI + row*144 + seg*16;
        const size_t g = qbase + row*64 + seg*8;
        cpa16(d,                 g_Qhi + g);
        cpa16(d + (A_QLO-A_QHI), g_Qlo + g);
    }
    prefetchKV(0, 0);
    CP_COMMIT();

    float o[2][4][4];
    #pragma unroll
    for (int i = 0; i < 2; i++)
        #pragma unroll
        for (int j = 0; j < 4; j++)
            #pragma unroll
            for (int k = 0; k < 4; k++) o[i][j][k] = 0.f;

    const int lrow = lane & 15;
    const int lc16 = (lane >> 4) * 16;
    const uint32_t aQhi = sb + A_QHI + (uint32_t)((wm*32 + lrow)*144) + lc16;
    const uint32_t aKhi = sb + A_KV0 + A_KHIo + (uint32_t)((wn*32 + lrow)*144) + lc16;
    const uint32_t aVhi = sb + A_KV0 + A_VHIo + (uint32_t)(lrow*144) + lc16 + (uint32_t)(wn*64);
    const uint32_t aPhi = sb + A_PHI + (uint32_t)((wm*32 + lrow)*144) + lc16;

    for (int c = 0; c < 16; c++) {
        if (c + 1 < 16) { prefetchKV(c + 1, (c + 1) & 1); CP_COMMIT(); }
        if (c + 1 < 16) { asm volatile("cp.async.wait_group 1;" ::: "memory"); }
        else            { asm volatile("cp.async.wait_group 0;" ::: "memory"); }
        __syncthreads();

        const uint32_t so = (uint32_t)(c & 1) * A_STAGE;

        // S = Q @ K^T  (K non-trans: B rows = keys)
        float s[2][4][4];
        #pragma unroll
        for (int i = 0; i < 2; i++)
            #pragma unroll
            for (int j = 0; j < 4; j++)
                #pragma unroll
                for (int k = 0; k < 4; k++) s[i][j][k] = 0.f;

        #pragma unroll
        for (int ks = 0; ks < 4; ks++) {
            uint32_t qh[2][4], ql[2][4];
            ldsm4(aQhi + ks*32,          qh[0]);
            ldsm4(aQhi + 16*144 + ks*32, qh[1]);
            ldsm4(aQhi + (A_QLO-A_QHI) + ks*32,          ql[0]);
            ldsm4(aQhi + (A_QLO-A_QHI) + 16*144 + ks*32, ql[1]);
            #pragma unroll
            for (int np = 0; np < 2; np++) {
                uint32_t kh[4], kl[4];
                ldsm4(aKhi + so + np*16*144 + ks*32, kh);
                ldsm4(aKhi + so + (A_KLOo-A_KHIo) + np*16*144 + ks*32, kl);
                // non-trans pairing: n-tile0 = {r0,r2}, n-tile1 = {r1,r3}
                #pragma unroll
                for (int mt = 0; mt < 2; mt++) {
                    mma16816(s[mt][np*2+0], qh[mt], kh[0], kh[2]);
                    mma16816(s[mt][np*2+1], qh[mt], kh[1], kh[3]);
                    mma16816(s[mt][np*2+0], qh[mt], kl[0], kl[2]);
                    mma16816(s[mt][np*2+1], qh[mt], kl[1], kl[3]);
                    mma16816(s[mt][np*2+0], ql[mt], kh[0], kh[2]);
                    mma16816(s[mt][np*2+1], ql[mt], kh[1], kh[3]);
                }
            }
        }

        // P = 2^S, row-sum partials, P -> smem hi/lo
        #pragma unroll
        for (int mt = 0; mt < 2; mt++) {
            float rs0 = 0.f, rs1 = 0.f;
            const int prow = wm*32 + mt*16 + (lane >> 2);
            #pragma unroll
            for (int nt = 0; nt < 4; nt++) {
                const float e0 = fast_exp2(s[mt][nt][0]);
                const float e1 = fast_exp2(s[mt][nt][1]);
                const float e2 = fast_exp2(s[mt][nt][2]);
                const float e3 = fast_exp2(s[mt][nt][3]);
                rs0 += e0 + e1;
                rs1 += e2 + e3;
                const int pcol = wn*32 + nt*8 + (lane & 3)*2;
                const uint32_t off0 = (uint32_t)(prow*144 + pcol*2);
                split2_store(smem + A_PHI + off0, smem + A_PLO + off0, e0, e1);
                const uint32_t off1 = off0 + 8*144;
                split2_store(smem + A_PHI + off1, smem + A_PLO + off1, e2, e3);
            }
            rs0 += __shfl_xor_sync(0xffffffffu, rs0, 1);
            rs0 += __shfl_xor_sync(0xffffffffu, rs0, 2);
            rs1 += __shfl_xor_sync(0xffffffffu, rs1, 1);
            rs1 += __shfl_xor_sync(0xffffffffu, rs1, 2);
            if ((lane & 3) == 0) {
                rsp[wn*128 + prow]     = rs0;
                rsp[wn*128 + prow + 8] = rs1;
            }
        }
        __syncthreads();
        if (tid < 128) rsa[tid] += rsp[tid] + rsp[128 + tid];

        // O += P @ V  (V trans: B = [key][d])
        #pragma unroll
        for (int ks = 0; ks < 4; ks++) {
            uint32_t ph[2][4], pl[2][4];
            ldsm4(aPhi + ks*32,          ph[0]);
            ldsm4(aPhi + 16*144 + ks*32, ph[1]);
            ldsm4(aPhi + (A_PLO-A_PHI) + ks*32,          pl[0]);
            ldsm4(aPhi + (A_PLO-A_PHI) + 16*144 + ks*32, pl[1]);
            #pragma unroll
            for (int np = 0; np < 2; np++) {
                uint32_t vh[4], vl[4];
                ldsm4t(aVhi + so + ks*16*144 + np*32, vh);
                ldsm4t(aVhi + so + (A_VLOo-A_VHIo) + ks*16*144 + np*32, vl);
                // trans pairing: n-tile0 = {r0,r1}, n-tile1 = {r2,r3}
                #pragma unroll
                for (int mt = 0; mt < 2; mt++) {
                    mma16816(o[mt][np*2+0], ph[mt], vh[0], vh[1]);
                    mma16816(o[mt][np*2+1], ph[mt], vh[2], vh[3]);
                    mma16816(o[mt][np*2+0], ph[mt], vl[0], vl[1]);
                    mma16816(o[mt][np*2+1], ph[mt], vl[2], vl[3]);
                    mma16816(o[mt][np*2+0], pl[mt], vh[0], vh[1]);
                    mma16816(o[mt][np*2+1], pl[mt], vh[2], vh[3]);
                }
            }
        }
        __syncthreads();   // stage + P reads done before overwrite
    }

    // Normalize + split-store AO (bf16 hi/lo)
    const int b = bh / HEADS;
    const int h = bh - b*HEADS;
    #pragma unroll
    for (int mt = 0; mt < 2; mt++) {
        const int row0 = wm*32 + mt*16 + (lane >> 2);
        const float inv0 = 1.f / rsa[row0];
        const float inv1 = 1.f / rsa[row0 + 8];
        #pragma unroll
        for (int nt = 0; nt < 4; nt++) {
            const int d = wn*32 + nt*8 + (lane & 3)*2;
            {
                const size_t idx = (size_t)(b*SEQ + q0 + row0)*INNER + h*DHEAD + d;
                __nv_bfloat162 h2, l2;
                split_pack(o[mt][nt][0]*inv0, o[mt][nt][1]*inv0, h2, l2);
                *(__nv_bfloat162*)(g_AOhi + idx) = h2;
                *(__nv_bfloat162*)(g_AOlo + idx) = l2;
            }
            {
                const size_t idx = (size_t)(b*SEQ + q0 + row0 + 8)*INNER + h*DHEAD + d;
                __nv_bfloat162 h2, l2;
                split_pack(o[mt][nt][2]*inv1, o[mt][nt][3]*inv1, h2, l2);
                *(__nv_bfloat162*)(g_AOhi + idx) = h2;
                *(__nv_bfloat162*)(g_AOlo + idx) = l2;
            }
        }
    }
}

// ---------------------------------------------------------------------------
// Launch
// ---------------------------------------------------------------------------
extern "C" void kernel_launch(void* const* d_in, const int* in_sizes, int n_in,
                              void* d_out, int out_size)
{
    const float* x     = (const float*)d_in[0];
    const float* w_qkv = (const float*)d_in[1];
    const float* w_out = (const float*)d_in[2];
    const float* b_out = (const float*)d_in[3];
    float* out = (float*)d_out;

    cudaFuncSetAttribute(gemm_tc<0>, cudaFuncAttributeMaxDynamicSharedMemorySize, G_SMEM_BYTES);
    cudaFuncSetAttribute(gemm_tc<1>, cudaFuncAttributeMaxDynamicSharedMemorySize, G_SMEM_BYTES);
    cudaFuncSetAttribute(attn_tc,    cudaFuncAttributeMaxDynamicSharedMemorySize, A_SMEM_BYTES);

    cvt_split<0><<<(MROWS*DIM)/1024, 256>>>(x, MROWS*DIM);
    cvt_split<1><<<(DIM*NQKV)/1024, 256>>>(w_qkv, DIM*NQKV);
    cvt_split<2><<<(INNER*DIM)/1024, 256>>>(w_out, INNER*DIM);

    dim3 g1(NQKV/128, MROWS/128);   // 18 x 64
    gemm_tc<0><<<g1, 256, G_SMEM_BYTES>>>(nullptr, nullptr);

    dim3 g2(SEQ/128, BATCH*HEADS);  // 8 x 96
    attn_tc<<<g2, 256, A_SMEM_BYTES>>>();

    dim3 g3(DIM/128, MROWS/128);    // 6 x 64
    gemm_tc<1><<<g3, 256, G_SMEM_BYTES>>>(b_out, out);
}